// round 1
// baseline (speedup 1.0000x reference)
#include <cuda_runtime.h>

// Scratch for the intermediate t4[i][n][l] (64*56*56 floats). __device__ global
// (no allocation in kernel_launch, per harness rules).
__device__ float g_t4[64 * 56 * 56];

// ---------------------------------------------------------------------------
// Kernel A: t4[i,n,l] = sum_{j=0..63, k=0..2} x[j, n, l+k-1] * w2[i,j,k]
// (zero padding on l). Grid: (ihalf=2, n=56). Block: 128 threads.
// Each thread computes a 2-channel x 7-column register tile.
// ---------------------------------------------------------------------------
__global__ __launch_bounds__(128) void conv_kernel(const float* __restrict__ x,
                                                   const float* __restrict__ w2) {
    __shared__ float xs[64 * 58];     // one spatial row, zero-padded: xs[j*58 + 1 + l]
    __shared__ float w2s[192 * 33];   // transposed weights: w2s[(j*3+k)*33 + i_local]

    const int n     = blockIdx.y;
    const int ihalf = blockIdx.x;
    const int ibase = ihalf * 32;
    const int tid   = threadIdx.x;

    // Load x row n for all 64 channels, with zero halo at cols 0 and 57.
    for (int idx = tid; idx < 64 * 58; idx += 128) {
        int j = idx / 58;
        int c = idx % 58;
        float v = 0.0f;
        if (c >= 1 && c <= 56) v = x[(j * 56 + n) * 56 + (c - 1)];
        xs[idx] = v;
    }
    // Load this block's 32 channels of w2, transposed to [jk][i] (+1 pad -> 33)
    // so the inner-loop reads are broadcast/conflict-free.
    for (int idx = tid; idx < 32 * 192; idx += 128) {
        int il = idx / 192;
        int jk = idx % 192;   // consecutive lanes -> consecutive jk: coalesced gmem read,
                              // smem write stride 33 -> conflict-free
        w2s[jk * 33 + il] = w2[(ibase + il) * 192 + jk];
    }
    __syncthreads();

    const int ip = tid >> 3;   // 0..15  (channel pair)
    const int lg = tid & 7;    // 0..7   (column group)
    const int l0 = lg * 7;     // output columns l0 .. l0+6

    float acc[2][7];
#pragma unroll
    for (int c = 0; c < 2; ++c)
#pragma unroll
        for (int t = 0; t < 7; ++t) acc[c][t] = 0.0f;

#pragma unroll 2
    for (int j = 0; j < 64; ++j) {
        // x window: padded cols l0 .. l0+8 (covers l+k for l in [l0,l0+6], k in [0,2])
        float xv[9];
#pragma unroll
        for (int t = 0; t < 9; ++t) xv[t] = xs[j * 58 + l0 + t];

#pragma unroll
        for (int c = 0; c < 2; ++c) {
            const int il = ip * 2 + c;
            const float wk0 = w2s[(j * 3 + 0) * 33 + il];
            const float wk1 = w2s[(j * 3 + 1) * 33 + il];
            const float wk2 = w2s[(j * 3 + 2) * 33 + il];
#pragma unroll
            for (int t = 0; t < 7; ++t) {
                acc[c][t] = fmaf(xv[t],     wk0,
                           fmaf(xv[t + 1], wk1,
                           fmaf(xv[t + 2], wk2, acc[c][t])));
            }
        }
    }

#pragma unroll
    for (int c = 0; c < 2; ++c) {
        const int i = ibase + ip * 2 + c;
#pragma unroll
        for (int t = 0; t < 7; ++t)
            g_t4[(i * 56 + n) * 56 + l0 + t] = acc[c][t];
    }
}

// ---------------------------------------------------------------------------
// Kernel B: out[i,m,l] = w1[i,0]*t4[i,(m-1)%56,l] + w1[i,1]*t4[i,(m-2)%56,l]
// ---------------------------------------------------------------------------
__global__ __launch_bounds__(256) void combine_kernel(const float* __restrict__ w1,
                                                      float* __restrict__ out) {
    int idx = blockIdx.x * 256 + threadIdx.x;
    if (idx >= 64 * 56 * 56) return;
    int l = idx % 56;
    int m = (idx / 56) % 56;
    int i = idx / (56 * 56);
    int m1 = (m + 55) % 56;  // m-1 mod 56
    int m2 = (m + 54) % 56;  // m-2 mod 56
    float a = g_t4[(i * 56 + m1) * 56 + l];
    float b = g_t4[(i * 56 + m2) * 56 + l];
    out[idx] = fmaf(w1[2 * i], a, w1[2 * i + 1] * b);
}

extern "C" void kernel_launch(void* const* d_in, const int* in_sizes, int n_in,
                              void* d_out, int out_size) {
    const float* x  = (const float*)d_in[0];   // (1,64,56,56)
    const float* w1 = (const float*)d_in[1];   // (64,2)
    const float* w2 = (const float*)d_in[2];   // (64,64,3)
    float* out = (float*)d_out;                // (1,64,56,56)

    dim3 gridA(2, 56);
    conv_kernel<<<gridA, 128>>>(x, w2);

    int total = 64 * 56 * 56;
    combine_kernel<<<(total + 255) / 256, 256>>>(w1, out);
}